// round 6
// baseline (speedup 1.0000x reference)
#include <cuda_runtime.h>
#include <cstdint>

#define T_STEPS 1000
#define HDIM    512
#define IDIM    13
#define FRAME   (512 * 512)

#define NT 16            // tiles along H
#define NCTA 128         // 8 x 16 tiles of 64x32
#define THREADS 128
#define ASTRIDE 516      // padded A row (floats): conflict-free frags, 16B-aligned rows

#define ALPHA_F 0.2f
#define OMA_F   0.8f
#define SIGMA_F 0.15811388300841898f   // sqrt(2/0.2)*0.05

struct SmemLayout {
    float  a[64][ASTRIDE];            // relu'd tf32 prev-state tile rows
    float2 wfrag[64][4][32];          // W_hh B-fragments (tf32 bits)
    float  xs[64 * IDIM];             // staged x rows (packed, stride 13)
    float  wih[IDIM][32];             // W_ih column slice
    float  biass[32];
};

__device__ float    g_scratch[2][FRAME];  // relu'd tf32 state, double buffered
__device__ unsigned g_count = 0;
__device__ unsigned g_phase = 0;

__device__ __forceinline__ void grid_barrier() {
    __threadfence();
    __syncthreads();
    if (threadIdx.x == 0) {
        unsigned ph;
        asm volatile("ld.acquire.gpu.u32 %0, [%1];" : "=r"(ph) : "l"(&g_phase) : "memory");
        unsigned arrived;
        asm volatile("atom.acq_rel.gpu.add.u32 %0, [%1], %2;"
                     : "=r"(arrived) : "l"(&g_count), "r"(1u) : "memory");
        if (arrived == NCTA - 1) {
            asm volatile("st.relaxed.gpu.u32 [%0], %1;" :: "l"(&g_count), "r"(0u) : "memory");
            asm volatile("red.release.gpu.add.u32 [%0], %1;" :: "l"(&g_phase), "r"(1u) : "memory");
        } else {
            unsigned cur;
            do {
                __nanosleep(64);
                asm volatile("ld.acquire.gpu.u32 %0, [%1];" : "=r"(cur) : "l"(&g_phase) : "memory");
            } while (cur == ph);
        }
    }
    __syncthreads();
}

__device__ __forceinline__ float tf32_rna(float f) {
    unsigned u;
    asm("cvt.rna.tf32.f32 %0, %1;" : "=r"(u) : "f"(f));
    return __uint_as_float(u);
}
__device__ __forceinline__ float relu_tf32(float f) {
    return tf32_rna(fmaxf(f, 0.0f));
}
template <int N>
__device__ __forceinline__ void wait_cp() {
    asm volatile("cp.async.wait_group %0;" :: "n"(N) : "memory");
}

#define MMA_TF32(D, A0, A1, A2, A3, B0, B1)                                      \
    asm volatile("mma.sync.aligned.m16n8k8.row.col.f32.tf32.tf32.f32 "           \
                 "{%0,%1,%2,%3}, {%4,%5,%6,%7}, {%8,%9}, {%0,%1,%2,%3};"         \
                 : "+f"(D[0]), "+f"(D[1]), "+f"(D[2]), "+f"(D[3])                \
                 : "r"(A0), "r"(A1), "r"(A2), "r"(A3), "r"(B0), "r"(B1))

__device__ __forceinline__ void do_group(const int j, const float* __restrict__ aptr,
                                         const SmemLayout* __restrict__ sm,
                                         const int lane, float (&acc)[4][4]) {
#pragma unroll
    for (int kk = 0; kk < 8; kk++) {
        const int kc = j * 8 + kk;
        unsigned a0 = __float_as_uint(aptr[kc * 8]);
        unsigned a1 = __float_as_uint(aptr[8 * ASTRIDE + kc * 8]);
        unsigned a2 = __float_as_uint(aptr[kc * 8 + 4]);
        unsigned a3 = __float_as_uint(aptr[8 * ASTRIDE + kc * 8 + 4]);
#pragma unroll
        for (int h = 0; h < 4; h++) {
            float2 b = sm->wfrag[kc][h][lane];
            MMA_TF32(acc[h], a0, a1, a2, a3, __float_as_uint(b.x), __float_as_uint(b.y));
        }
    }
}

__global__ void __launch_bounds__(THREADS, 1)
rnn_kernel(const float* __restrict__ x,       // [T,B,13]
           const float* __restrict__ init,    // [B,H]
           const float* __restrict__ noise,   // [T,B,H]
           const float* __restrict__ wih_g,   // [13,H]
           const float* __restrict__ whh_g,   // [H,H]
           const float* __restrict__ bias_g,  // [H] (1,H)
           float* __restrict__ out)           // [T+1,B,H]
{
    extern __shared__ char smem_raw[];
    SmemLayout* sm = reinterpret_cast<SmemLayout*>(smem_raw);

    const int tid  = threadIdx.x;
    const int mt   = blockIdx.x / NT;
    const int nt   = blockIdx.x % NT;
    const int m0   = mt * 64;
    const int n0   = nt * 32;
    const int w    = tid >> 5;
    const int lane = tid & 31;
    const int g    = lane >> 2;
    const int tg   = lane & 3;
    const int c0   = tg * 2;
    const int r0l  = w * 16 + g;      // local row of this lane's upper half

    // ---------------- one-time setup ----------------
    for (int i = tid; i < IDIM * 32; i += THREADS) {
        int r = i / 32, c = i % 32;
        sm->wih[r][c] = wih_g[r * HDIM + n0 + c];
    }
    if (tid < 32) sm->biass[tid] = bias_g[n0 + tid];

    // W_hh B-fragments: lane holds (W[k0][n], W[k0+4][n]), diag masked, tf32-rounded
    for (int i = tid; i < 64 * 4 * 32; i += THREADS) {
        int ln = i & 31, h = (i >> 5) & 3, kc = i >> 7;
        int k0 = kc * 8 + (ln & 3);
        int n  = n0 + h * 8 + (ln >> 2);
        float v0 = (k0 == n)     ? 0.0f : whh_g[(size_t)k0 * HDIM + n];
        float v1 = (k0 + 4 == n) ? 0.0f : whh_g[(size_t)(k0 + 4) * HDIM + n];
        float2 p; p.x = tf32_rna(v0); p.y = tf32_rna(v1);
        sm->wfrag[kc][h][ln] = p;
    }

    // out[0] = init ; scratch[0] = relu_tf32(init)   (own tile)
    for (int it = 0; it < 4; it++) {
        int i = tid + it * THREADS;          // 0..511 float4 slots
        int r = i >> 3, cc = (i & 7) * 4;
        size_t gi = (size_t)(m0 + r) * HDIM + n0 + cc;
        float4 v = *reinterpret_cast<const float4*>(init + gi);
        *reinterpret_cast<float4*>(out + gi) = v;
        float4 rv;
        rv.x = relu_tf32(v.x); rv.y = relu_tf32(v.y);
        rv.z = relu_tf32(v.z); rv.w = relu_tf32(v.w);
        *reinterpret_cast<float4*>(&g_scratch[0][gi]) = rv;
    }

    // stprev registers: this lane's 16 output elements of the state
    float stprev[4][4];
    {
        const float* ip = init + (size_t)(m0 + r0l) * HDIM + n0;
#pragma unroll
        for (int h = 0; h < 4; h++) {
            int col = h * 8 + c0;
            float2 a = *reinterpret_cast<const float2*>(ip + col);
            float2 b = *reinterpret_cast<const float2*>(ip + 8 * HDIM + col);
            stprev[h][0] = a.x; stprev[h][1] = a.y;
            stprev[h][2] = b.x; stprev[h][3] = b.y;
        }
    }

    grid_barrier();

    const unsigned a_base = (unsigned)__cvta_generic_to_shared(&sm->a[0][0]);
    const float* aptr = &sm->a[r0l][tg];

    for (int t = 1; t <= T_STEPS; t++) {
        const int rsel = (t - 1) & 1, wsel = t & 1;
        const float* src = g_scratch[rsel] + (size_t)m0 * HDIM;

        // stage A tile: 8 cp.async groups of 64 columns x 64 rows
#pragma unroll
        for (int gj = 0; gj < 8; gj++) {
#pragma unroll
            for (int it = 0; it < 8; it++) {
                int i  = tid + it * THREADS;  // 0..1023
                int r  = i >> 4;
                int cc = gj * 64 + (i & 15) * 4;
                const float* gp = src + (size_t)r * HDIM + cc;
                unsigned sp = a_base + (unsigned)((r * ASTRIDE + cc) * 4);
                asm volatile("cp.async.cg.shared.global [%0], [%1], 16;"
                             :: "r"(sp), "l"(gp) : "memory");
            }
            asm volatile("cp.async.commit_group;" ::: "memory");
        }

        // stage x rows (packed [64][13]) while copies fly
        {
            const float* xq = x + (size_t)(t - 1) * 512 * IDIM + (size_t)m0 * IDIM;
            for (int i = tid; i < 64 * IDIM; i += THREADS) sm->xs[i] = xq[i];
        }

        wait_cp<7>();
        __syncthreads();   // group 0 + xs visible to all

        // acc := bias + x @ W_ih  (overlaps with groups 1..7 landing)
        float acc[4][4];
#pragma unroll
        for (int h = 0; h < 4; h++) {
            int col = h * 8 + c0;
            float b0 = sm->biass[col], b1 = sm->biass[col + 1];
            acc[h][0] = b0; acc[h][1] = b1; acc[h][2] = b0; acc[h][3] = b1;
        }
#pragma unroll
        for (int i = 0; i < IDIM; i++) {
            float x0 = sm->xs[r0l * IDIM + i];
            float x1 = sm->xs[(r0l + 8) * IDIM + i];
#pragma unroll
            for (int h = 0; h < 4; h++) {
                int col = h * 8 + c0;
                float w0 = sm->wih[i][col], w1 = sm->wih[i][col + 1];
                acc[h][0] += x0 * w0; acc[h][1] += x0 * w1;
                acc[h][2] += x1 * w0; acc[h][3] += x1 * w1;
            }
        }

        // pipelined mma over 8 k64 groups
        do_group(0, aptr, sm, lane, acc);
        wait_cp<6>(); __syncthreads(); do_group(1, aptr, sm, lane, acc);
        wait_cp<5>(); __syncthreads(); do_group(2, aptr, sm, lane, acc);
        wait_cp<4>(); __syncthreads(); do_group(3, aptr, sm, lane, acc);
        wait_cp<3>(); __syncthreads(); do_group(4, aptr, sm, lane, acc);
        wait_cp<2>(); __syncthreads(); do_group(5, aptr, sm, lane, acc);
        wait_cp<1>(); __syncthreads(); do_group(6, aptr, sm, lane, acc);
        wait_cp<0>(); __syncthreads(); do_group(7, aptr, sm, lane, acc);

        // epilogue: leak-integrate, write out[t] and scratch[wsel]
        {
            const size_t rowoff = (size_t)(m0 + r0l) * HDIM + n0;
            const float* nz  = noise + (size_t)(t - 1) * FRAME + rowoff;
            float*       op  = out   + (size_t)t * FRAME + rowoff;
            float*       scw = g_scratch[wsel] + rowoff;
#pragma unroll
            for (int h = 0; h < 4; h++) {
                int col = h * 8 + c0;
                float2 nA = *reinterpret_cast<const float2*>(nz + col);
                float2 nB = *reinterpret_cast<const float2*>(nz + 8 * HDIM + col);
                float s0 = OMA_F * stprev[h][0] + ALPHA_F * (acc[h][0] + SIGMA_F * nA.x);
                float s1 = OMA_F * stprev[h][1] + ALPHA_F * (acc[h][1] + SIGMA_F * nA.y);
                float s2 = OMA_F * stprev[h][2] + ALPHA_F * (acc[h][2] + SIGMA_F * nB.x);
                float s3 = OMA_F * stprev[h][3] + ALPHA_F * (acc[h][3] + SIGMA_F * nB.y);
                float2 oA; oA.x = s0; oA.y = s1;
                float2 oB; oB.x = s2; oB.y = s3;
                *reinterpret_cast<float2*>(op + col)            = oA;
                *reinterpret_cast<float2*>(op + 8 * HDIM + col) = oB;
                float2 rA; rA.x = relu_tf32(s0); rA.y = relu_tf32(s1);
                float2 rB; rB.x = relu_tf32(s2); rB.y = relu_tf32(s3);
                *reinterpret_cast<float2*>(scw + col)            = rA;
                *reinterpret_cast<float2*>(scw + 8 * HDIM + col) = rB;
                stprev[h][0] = s0; stprev[h][1] = s1;
                stprev[h][2] = s2; stprev[h][3] = s3;
            }
        }

        grid_barrier();   // scratch[wsel] published to everyone
    }
}

extern "C" void kernel_launch(void* const* d_in, const int* in_sizes, int n_in,
                              void* d_out, int out_size) {
    const float* x     = (const float*)d_in[0];
    const float* init  = (const float*)d_in[1];
    const float* noise = (const float*)d_in[2];
    const float* wih   = (const float*)d_in[3];
    const float* whh   = (const float*)d_in[4];
    const float* bias  = (const float*)d_in[5];
    float* out = (float*)d_out;

    cudaFuncSetAttribute(rnn_kernel, cudaFuncAttributeMaxDynamicSharedMemorySize,
                         (int)sizeof(SmemLayout));
    rnn_kernel<<<NCTA, THREADS, sizeof(SmemLayout)>>>(x, init, noise, wih, whh, bias, out);
}

// round 7
// speedup vs baseline: 1.0152x; 1.0152x over previous
#include <cuda_runtime.h>
#include <cstdint>

#define T_STEPS 1000
#define HDIM    512
#define IDIM    13
#define FRAME   (512 * 512)

#define NT 16            // tiles along H
#define NCTA 128         // 8 x 16 tiles of 64x32
#define THREADS 128
#define ASTRIDE 516      // padded A row (floats): conflict-free frags, 16B-aligned rows

#define ALPHA_F 0.2f
#define OMA_F   0.8f
#define SIGMA_F 0.15811388300841898f   // sqrt(2/0.2)*0.05

struct SmemLayout {
    float  a[64][ASTRIDE];            // relu'd tf32 prev-state tile rows
    float2 wfrag[64][4][32];          // W_hh B-fragments (tf32 bits)
    float  xs[64 * IDIM];             // staged x rows (packed, stride 13)
    float  wih[IDIM][32];             // W_ih column slice
    float  biass[32];
};

__device__ float    g_scratch[2][FRAME];  // relu'd tf32 state, double buffered
__device__ unsigned g_count = 0;
__device__ unsigned g_phase = 0;

__device__ __forceinline__ void grid_barrier() {
    __threadfence();
    __syncthreads();
    if (threadIdx.x == 0) {
        unsigned ph;
        asm volatile("ld.acquire.gpu.u32 %0, [%1];" : "=r"(ph) : "l"(&g_phase) : "memory");
        unsigned arrived;
        asm volatile("atom.acq_rel.gpu.add.u32 %0, [%1], %2;"
                     : "=r"(arrived) : "l"(&g_count), "r"(1u) : "memory");
        if (arrived == NCTA - 1) {
            asm volatile("st.relaxed.gpu.u32 [%0], %1;" :: "l"(&g_count), "r"(0u) : "memory");
            asm volatile("red.release.gpu.add.u32 [%0], %1;" :: "l"(&g_phase), "r"(1u) : "memory");
        } else {
            unsigned cur;
            do {
                __nanosleep(64);
                asm volatile("ld.acquire.gpu.u32 %0, [%1];" : "=r"(cur) : "l"(&g_phase) : "memory");
            } while (cur == ph);
        }
    }
    __syncthreads();
}

__device__ __forceinline__ float tf32_rna(float f) {
    unsigned u;
    asm("cvt.rna.tf32.f32 %0, %1;" : "=r"(u) : "f"(f));
    return __uint_as_float(u);
}
__device__ __forceinline__ float relu_tf32(float f) {
    return tf32_rna(fmaxf(f, 0.0f));
}
template <int N>
__device__ __forceinline__ void wait_cp() {
    asm volatile("cp.async.wait_group %0;" :: "n"(N) : "memory");
}

#define MMA_TF32(D, A0, A1, A2, A3, B0, B1)                                      \
    asm volatile("mma.sync.aligned.m16n8k8.row.col.f32.tf32.tf32.f32 "           \
                 "{%0,%1,%2,%3}, {%4,%5,%6,%7}, {%8,%9}, {%0,%1,%2,%3};"         \
                 : "+f"(D[0]), "+f"(D[1]), "+f"(D[2]), "+f"(D[3])                \
                 : "r"(A0), "r"(A1), "r"(A2), "r"(A3), "r"(B0), "r"(B1))

__device__ __forceinline__ void do_group(const int j, const float* __restrict__ aptr,
                                         const SmemLayout* __restrict__ sm,
                                         const int lane, float (&acc)[4][4]) {
#pragma unroll
    for (int kk = 0; kk < 8; kk++) {
        const int kc = j * 8 + kk;
        unsigned a0 = __float_as_uint(aptr[kc * 8]);
        unsigned a1 = __float_as_uint(aptr[8 * ASTRIDE + kc * 8]);
        unsigned a2 = __float_as_uint(aptr[kc * 8 + 4]);
        unsigned a3 = __float_as_uint(aptr[8 * ASTRIDE + kc * 8 + 4]);
#pragma unroll
        for (int h = 0; h < 4; h++) {
            float2 b = sm->wfrag[kc][h][lane];
            MMA_TF32(acc[h], a0, a1, a2, a3, __float_as_uint(b.x), __float_as_uint(b.y));
        }
    }
}

__global__ void __launch_bounds__(THREADS, 1)
rnn_kernel(const float* __restrict__ x,       // [T,B,13]
           const float* __restrict__ init,    // [B,H]
           const float* __restrict__ noise,   // [T,B,H]
           const float* __restrict__ wih_g,   // [13,H]
           const float* __restrict__ whh_g,   // [H,H]
           const float* __restrict__ bias_g,  // [H] (1,H)
           float* __restrict__ out)           // [T+1,B,H]
{
    extern __shared__ char smem_raw[];
    SmemLayout* sm = reinterpret_cast<SmemLayout*>(smem_raw);

    const int tid  = threadIdx.x;
    const int mt   = blockIdx.x / NT;
    const int nt   = blockIdx.x % NT;
    const int m0   = mt * 64;
    const int n0   = nt * 32;
    const int w    = tid >> 5;
    const int lane = tid & 31;
    const int g    = lane >> 2;
    const int tg   = lane & 3;
    const int c0   = tg * 2;
    const int r0l  = w * 16 + g;      // local row of this lane's upper half

    // ---------------- one-time setup ----------------
    for (int i = tid; i < IDIM * 32; i += THREADS) {
        int r = i / 32, c = i % 32;
        sm->wih[r][c] = wih_g[r * HDIM + n0 + c];
    }
    if (tid < 32) sm->biass[tid] = bias_g[n0 + tid];

    // W_hh B-fragments: lane holds (W[k0][n], W[k0+4][n]), diag masked, tf32-rounded
    for (int i = tid; i < 64 * 4 * 32; i += THREADS) {
        int ln = i & 31, h = (i >> 5) & 3, kc = i >> 7;
        int k0 = kc * 8 + (ln & 3);
        int n  = n0 + h * 8 + (ln >> 2);
        float v0 = (k0 == n)     ? 0.0f : whh_g[(size_t)k0 * HDIM + n];
        float v1 = (k0 + 4 == n) ? 0.0f : whh_g[(size_t)(k0 + 4) * HDIM + n];
        float2 p; p.x = tf32_rna(v0); p.y = tf32_rna(v1);
        sm->wfrag[kc][h][ln] = p;
    }

    // out[0] = init ; scratch[0] = relu_tf32(init)   (own tile)
    for (int it = 0; it < 4; it++) {
        int i = tid + it * THREADS;          // 0..511 float4 slots
        int r = i >> 3, cc = (i & 7) * 4;
        size_t gi = (size_t)(m0 + r) * HDIM + n0 + cc;
        float4 v = *reinterpret_cast<const float4*>(init + gi);
        *reinterpret_cast<float4*>(out + gi) = v;
        float4 rv;
        rv.x = relu_tf32(v.x); rv.y = relu_tf32(v.y);
        rv.z = relu_tf32(v.z); rv.w = relu_tf32(v.w);
        *reinterpret_cast<float4*>(&g_scratch[0][gi]) = rv;
    }

    // stprev registers: this lane's 16 output elements of the state
    float stprev[4][4];
    {
        const float* ip = init + (size_t)(m0 + r0l) * HDIM + n0;
#pragma unroll
        for (int h = 0; h < 4; h++) {
            int col = h * 8 + c0;
            float2 a = *reinterpret_cast<const float2*>(ip + col);
            float2 b = *reinterpret_cast<const float2*>(ip + 8 * HDIM + col);
            stprev[h][0] = a.x; stprev[h][1] = a.y;
            stprev[h][2] = b.x; stprev[h][3] = b.y;
        }
    }

    grid_barrier();

    const unsigned a_base = (unsigned)__cvta_generic_to_shared(&sm->a[0][0]);
    const float* aptr = &sm->a[r0l][tg];

    for (int t = 1; t <= T_STEPS; t++) {
        const int rsel = (t - 1) & 1, wsel = t & 1;
        const float* src = g_scratch[rsel] + (size_t)m0 * HDIM;

        // stage A tile: 8 cp.async groups of 64 columns x 64 rows
#pragma unroll
        for (int gj = 0; gj < 8; gj++) {
#pragma unroll
            for (int it = 0; it < 8; it++) {
                int i  = tid + it * THREADS;  // 0..1023
                int r  = i >> 4;
                int cc = gj * 64 + (i & 15) * 4;
                const float* gp = src + (size_t)r * HDIM + cc;
                unsigned sp = a_base + (unsigned)((r * ASTRIDE + cc) * 4);
                asm volatile("cp.async.cg.shared.global [%0], [%1], 16;"
                             :: "r"(sp), "l"(gp) : "memory");
            }
            asm volatile("cp.async.commit_group;" ::: "memory");
        }

        // stage x rows (packed [64][13]) while copies fly
        {
            const float* xq = x + (size_t)(t - 1) * 512 * IDIM + (size_t)m0 * IDIM;
            for (int i = tid; i < 64 * IDIM; i += THREADS) sm->xs[i] = xq[i];
        }

        wait_cp<7>();
        __syncthreads();   // group 0 + xs visible to all

        // acc := bias + x @ W_ih  (overlaps with groups 1..7 landing)
        float acc[4][4];
#pragma unroll
        for (int h = 0; h < 4; h++) {
            int col = h * 8 + c0;
            float b0 = sm->biass[col], b1 = sm->biass[col + 1];
            acc[h][0] = b0; acc[h][1] = b1; acc[h][2] = b0; acc[h][3] = b1;
        }
#pragma unroll
        for (int i = 0; i < IDIM; i++) {
            float x0 = sm->xs[r0l * IDIM + i];
            float x1 = sm->xs[(r0l + 8) * IDIM + i];
#pragma unroll
            for (int h = 0; h < 4; h++) {
                int col = h * 8 + c0;
                float w0 = sm->wih[i][col], w1 = sm->wih[i][col + 1];
                acc[h][0] += x0 * w0; acc[h][1] += x0 * w1;
                acc[h][2] += x1 * w0; acc[h][3] += x1 * w1;
            }
        }

        // pipelined mma over 8 k64 groups
        do_group(0, aptr, sm, lane, acc);
        wait_cp<6>(); __syncthreads(); do_group(1, aptr, sm, lane, acc);
        wait_cp<5>(); __syncthreads(); do_group(2, aptr, sm, lane, acc);
        wait_cp<4>(); __syncthreads(); do_group(3, aptr, sm, lane, acc);
        wait_cp<3>(); __syncthreads(); do_group(4, aptr, sm, lane, acc);
        wait_cp<2>(); __syncthreads(); do_group(5, aptr, sm, lane, acc);
        wait_cp<1>(); __syncthreads(); do_group(6, aptr, sm, lane, acc);
        wait_cp<0>(); __syncthreads(); do_group(7, aptr, sm, lane, acc);

        // epilogue: leak-integrate, write out[t] and scratch[wsel]
        {
            const size_t rowoff = (size_t)(m0 + r0l) * HDIM + n0;
            const float* nz  = noise + (size_t)(t - 1) * FRAME + rowoff;
            float*       op  = out   + (size_t)t * FRAME + rowoff;
            float*       scw = g_scratch[wsel] + rowoff;
#pragma unroll
            for (int h = 0; h < 4; h++) {
                int col = h * 8 + c0;
                float2 nA = *reinterpret_cast<const float2*>(nz + col);
                float2 nB = *reinterpret_cast<const float2*>(nz + 8 * HDIM + col);
                float s0 = OMA_F * stprev[h][0] + ALPHA_F * (acc[h][0] + SIGMA_F * nA.x);
                float s1 = OMA_F * stprev[h][1] + ALPHA_F * (acc[h][1] + SIGMA_F * nA.y);
                float s2 = OMA_F * stprev[h][2] + ALPHA_F * (acc[h][2] + SIGMA_F * nB.x);
                float s3 = OMA_F * stprev[h][3] + ALPHA_F * (acc[h][3] + SIGMA_F * nB.y);
                float2 oA; oA.x = s0; oA.y = s1;
                float2 oB; oB.x = s2; oB.y = s3;
                *reinterpret_cast<float2*>(op + col)            = oA;
                *reinterpret_cast<float2*>(op + 8 * HDIM + col) = oB;
                float2 rA; rA.x = relu_tf32(s0); rA.y = relu_tf32(s1);
                float2 rB; rB.x = relu_tf32(s2); rB.y = relu_tf32(s3);
                *reinterpret_cast<float2*>(scw + col)            = rA;
                *reinterpret_cast<float2*>(scw + 8 * HDIM + col) = rB;
                stprev[h][0] = s0; stprev[h][1] = s1;
                stprev[h][2] = s2; stprev[h][3] = s3;
            }
        }

        grid_barrier();   // scratch[wsel] published to everyone
    }
}

extern "C" void kernel_launch(void* const* d_in, const int* in_sizes, int n_in,
                              void* d_out, int out_size) {
    const float* x     = (const float*)d_in[0];
    const float* init  = (const float*)d_in[1];
    const float* noise = (const float*)d_in[2];
    const float* wih   = (const float*)d_in[3];
    const float* whh   = (const float*)d_in[4];
    const float* bias  = (const float*)d_in[5];
    float* out = (float*)d_out;

    cudaFuncSetAttribute(rnn_kernel, cudaFuncAttributeMaxDynamicSharedMemorySize,
                         (int)sizeof(SmemLayout));
    rnn_kernel<<<NCTA, THREADS, sizeof(SmemLayout)>>>(x, init, noise, wih, whh, bias, out);
}

// round 8
// speedup vs baseline: 1.2504x; 1.2316x over previous
#include <cuda_runtime.h>
#include <cuda_fp16.h>
#include <cstdint>

#define T_STEPS 1000
#define HDIM    512
#define IDIM    13
#define FRAME   (512 * 512)

#define NT      16          // tiles along H (N)
#define NCTA    128         // 8 x 16 grid of 64x32 tiles
#define THREADS 256         // 8 warps: 0-3 = K[0,256), 4-7 = K[256,512)
#define ASTRH   520         // padded A row in halves (conflict-free)

#define ALPHA_F 0.2f
#define OMA_F   0.8f
#define SIGMA_F 0.15811388300841898f   // sqrt(2/0.2)*0.05

struct SmemLayout {
    __half a[64][ASTRH];          // relu'd fp16 prev-state tile rows   66560 B
    uint2  wfrag[32][4][32];      // W_hh B-fragments (fp16x2 pairs)    32768 B
    float4 redsum[4][4][32];      // K-split partial sums                8192 B
    float  xs[64 * IDIM];         // staged x rows (packed)              3328 B
    float  wih[IDIM][32];         // W_ih column slice                   1664 B
    float  biass[32];
};

__device__ __half   g_scratch[2][FRAME];   // relu'd fp16 state, double buffered
__device__ unsigned g_sync[64];            // [0]=count, [32]=phase (separate lines)

__device__ __forceinline__ void grid_barrier() {
    __threadfence();
    __syncthreads();
    if (threadIdx.x == 0) {
        unsigned* cnt = &g_sync[0];
        unsigned* phs = &g_sync[32];
        unsigned ph;
        asm volatile("ld.acquire.gpu.u32 %0, [%1];" : "=r"(ph) : "l"(phs) : "memory");
        unsigned arrived;
        asm volatile("atom.acq_rel.gpu.add.u32 %0, [%1], %2;"
                     : "=r"(arrived) : "l"(cnt), "r"(1u) : "memory");
        if (arrived == NCTA - 1) {
            asm volatile("st.relaxed.gpu.u32 [%0], %1;" :: "l"(cnt), "r"(0u) : "memory");
            asm volatile("red.release.gpu.add.u32 [%0], %1;" :: "l"(phs), "r"(1u) : "memory");
        } else {
            unsigned cur;
            do {
                asm volatile("ld.acquire.gpu.u32 %0, [%1];" : "=r"(cur) : "l"(phs) : "memory");
            } while (cur == ph);
        }
    }
    __syncthreads();
}

template <int N>
__device__ __forceinline__ void wait_cp() {
    asm volatile("cp.async.wait_group %0;" :: "n"(N) : "memory");
}
__device__ __forceinline__ void bar_named(int id) {
    asm volatile("bar.sync %0, 128;" :: "r"(id) : "memory");
}

#define MMA_F16(D, A0, A1, A2, A3, B0, B1)                                       \
    asm volatile("mma.sync.aligned.m16n8k16.row.col.f32.f16.f16.f32 "            \
                 "{%0,%1,%2,%3}, {%4,%5,%6,%7}, {%8,%9}, {%0,%1,%2,%3};"         \
                 : "+f"(D[0]), "+f"(D[1]), "+f"(D[2]), "+f"(D[3])                 \
                 : "r"(A0), "r"(A1), "r"(A2), "r"(A3), "r"(B0), "r"(B1))

// one chunk = 4 k16 steps x 4 n8 blocks
__device__ __forceinline__ void do_chunk(const int cidx, const int kgoff, const int koffh,
                                         const __half* __restrict__ aptr,
                                         const SmemLayout* __restrict__ sm,
                                         const int lane, float (&acc)[4][4]) {
#pragma unroll
    for (int kk = 0; kk < 4; kk++) {
        const int kcl = cidx * 4 + kk;
        const int kb  = koffh + kcl * 16;
        unsigned u0 = *reinterpret_cast<const unsigned*>(aptr + kb);
        unsigned u1 = *reinterpret_cast<const unsigned*>(aptr + 8 * ASTRH + kb);
        unsigned u2 = *reinterpret_cast<const unsigned*>(aptr + kb + 8);
        unsigned u3 = *reinterpret_cast<const unsigned*>(aptr + 8 * ASTRH + kb + 8);
#pragma unroll
        for (int h = 0; h < 4; h++) {
            uint2 b = sm->wfrag[kgoff + kcl][h][lane];
            MMA_F16(acc[h], u0, u1, u2, u3, b.x, b.y);
        }
    }
}

__global__ void __launch_bounds__(THREADS, 1)
rnn_kernel(const float* __restrict__ x,       // [T,B,13]
           const float* __restrict__ init,    // [B,H]
           const float* __restrict__ noise,   // [T,B,H]
           const float* __restrict__ wih_g,   // [13,H]
           const float* __restrict__ whh_g,   // [H,H]
           const float* __restrict__ bias_g,  // [1,H]
           float* __restrict__ out)           // [T+1,B,H]
{
    extern __shared__ char smem_raw[];
    SmemLayout* sm = reinterpret_cast<SmemLayout*>(smem_raw);

    const int tid  = threadIdx.x;
    const int mt   = blockIdx.x / NT;
    const int nt   = blockIdx.x % NT;
    const int m0   = mt * 64;
    const int n0   = nt * 32;
    const int wid  = tid >> 5;
    const int lane = tid & 31;
    const int half = wid >> 2;      // 0: K[0,256)  1: K[256,512)
    const int wq   = wid & 3;       // m-block within tile
    const int G    = lane >> 2;
    const int T4   = lane & 3;
    const int c0   = T4 * 2;
    const int r0l  = wq * 16 + G;   // local row (upper half of fragment)
    const int koffh = half * 256;   // k offset in halves
    const int kgoff = half * 16;    // wfrag kc offset

    // ---------------- one-time setup ----------------
    for (int i = tid; i < IDIM * 32; i += THREADS) {
        int r = i / 32, c = i % 32;
        sm->wih[r][c] = wih_g[r * HDIM + n0 + c];
    }
    if (tid < 32) sm->biass[tid] = bias_g[n0 + tid];

    // W_hh fragments (fp16, diag masked). m16n8k16 B layout:
    // reg0 = {W[kb+2T][n], W[kb+2T+1][n]}, reg1 = {W[kb+2T+8][n], W[kb+2T+9][n]}
    for (int i = tid; i < 32 * 4 * 32; i += THREADS) {
        int ln = i & 31, h = (i >> 5) & 3, kc = i >> 7;
        int Tl = ln & 3, Gl = ln >> 2;
        int n  = n0 + h * 8 + Gl;
        int kb = kc * 16 + 2 * Tl;
        float v00 = (kb     == n) ? 0.0f : whh_g[(size_t)kb * HDIM + n];
        float v01 = (kb + 1 == n) ? 0.0f : whh_g[(size_t)(kb + 1) * HDIM + n];
        float v10 = (kb + 8 == n) ? 0.0f : whh_g[(size_t)(kb + 8) * HDIM + n];
        float v11 = (kb + 9 == n) ? 0.0f : whh_g[(size_t)(kb + 9) * HDIM + n];
        __half2 p0 = __floats2half2_rn(v00, v01);
        __half2 p1 = __floats2half2_rn(v10, v11);
        uint2 p;
        p.x = *reinterpret_cast<unsigned*>(&p0);
        p.y = *reinterpret_cast<unsigned*>(&p1);
        sm->wfrag[kc][h][ln] = p;
    }

    // out[0] = init ; scratch[0] = fp16(relu(init))  (own 64x32 tile)
    for (int i = tid; i < 64 * 32; i += THREADS) {
        int r = i >> 5, c = i & 31;
        size_t gi = (size_t)(m0 + r) * HDIM + n0 + c;
        float v = init[gi];
        out[gi] = v;
        g_scratch[0][gi] = __float2half_rn(fmaxf(v, 0.0f));
    }

    // stprev registers (A-warps): this lane's 16 state elements
    float stprev[4][4];
    if (half == 0) {
        const float* ip = init + (size_t)(m0 + r0l) * HDIM + n0;
#pragma unroll
        for (int h = 0; h < 4; h++) {
            int col = h * 8 + c0;
            float2 a = *reinterpret_cast<const float2*>(ip + col);
            float2 b = *reinterpret_cast<const float2*>(ip + 8 * HDIM + col);
            stprev[h][0] = a.x; stprev[h][1] = a.y;
            stprev[h][2] = b.x; stprev[h][3] = b.y;
        }
    }

    grid_barrier();

    const unsigned a_base = (unsigned)__cvta_generic_to_shared(&sm->a[0][0]);
    const __half* aptr = &sm->a[r0l][c0];
    const size_t rowoff = (size_t)(m0 + r0l) * HDIM + n0;

    for (int t = 1; t <= T_STEPS; t++) {
        const int rsel = (t - 1) & 1, wsel = t & 1;
        const __half* src = g_scratch[rsel] + (size_t)m0 * HDIM;

        // ---- stage own K-half of A tile: 4 cp.async groups of 64 half-cols ----
        {
            const int lt = tid & 127;
#pragma unroll
            for (int gj = 0; gj < 4; gj++) {
#pragma unroll
                for (int it = 0; it < 4; it++) {
                    int i  = lt + it * 128;              // 0..511
                    int r  = i >> 3;
                    int ch = koffh + gj * 64 + (i & 7) * 8;
                    const __half* gp = src + (size_t)r * HDIM + ch;
                    unsigned sp = a_base + (unsigned)((r * ASTRH + ch) * 2);
                    asm volatile("cp.async.cg.shared.global [%0], [%1], 16;"
                                 :: "r"(sp), "l"(gp) : "memory");
                }
                asm volatile("cp.async.commit_group;" ::: "memory");
            }
        }

        float2 nzv[8];
        if (half == 0) {
            // prefetch noise into registers (lands during GEMM)
            const float* nz = noise + (size_t)(t - 1) * FRAME + rowoff;
#pragma unroll
            for (int h = 0; h < 4; h++) {
                nzv[h * 2]     = *reinterpret_cast<const float2*>(nz + h * 8 + c0);
                nzv[h * 2 + 1] = *reinterpret_cast<const float2*>(nz + 8 * HDIM + h * 8 + c0);
            }
            // stage x rows (A-threads only; visibility via bar.sync 1)
            const float* xq = x + ((size_t)(t - 1) * 512 + m0) * IDIM;
            for (int i = tid; i < 64 * IDIM; i += 128) sm->xs[i] = xq[i];
        }

        float acc[4][4];
        if (half == 0) {
            wait_cp<3>(); bar_named(1);
            // acc := bias + x @ W_ih (overlaps remaining groups)
#pragma unroll
            for (int h = 0; h < 4; h++) {
                int col = h * 8 + c0;
                float b0 = sm->biass[col], b1 = sm->biass[col + 1];
                acc[h][0] = b0; acc[h][1] = b1; acc[h][2] = b0; acc[h][3] = b1;
            }
#pragma unroll
            for (int i = 0; i < IDIM; i++) {
                float x0 = sm->xs[r0l * IDIM + i];
                float x1 = sm->xs[(r0l + 8) * IDIM + i];
#pragma unroll
                for (int h = 0; h < 4; h++) {
                    int col = h * 8 + c0;
                    float w0 = sm->wih[i][col], w1 = sm->wih[i][col + 1];
                    acc[h][0] += x0 * w0; acc[h][1] += x0 * w1;
                    acc[h][2] += x1 * w0; acc[h][3] += x1 * w1;
                }
            }
            do_chunk(0, kgoff, koffh, aptr, sm, lane, acc);
            wait_cp<2>(); bar_named(1); do_chunk(1, kgoff, koffh, aptr, sm, lane, acc);
            wait_cp<1>(); bar_named(1); do_chunk(2, kgoff, koffh, aptr, sm, lane, acc);
            wait_cp<0>(); bar_named(1); do_chunk(3, kgoff, koffh, aptr, sm, lane, acc);
        } else {
#pragma unroll
            for (int h = 0; h < 4; h++)
                acc[h][0] = acc[h][1] = acc[h][2] = acc[h][3] = 0.0f;
            wait_cp<3>(); bar_named(2); do_chunk(0, kgoff, koffh, aptr, sm, lane, acc);
            wait_cp<2>(); bar_named(2); do_chunk(1, kgoff, koffh, aptr, sm, lane, acc);
            wait_cp<1>(); bar_named(2); do_chunk(2, kgoff, koffh, aptr, sm, lane, acc);
            wait_cp<0>(); bar_named(2); do_chunk(3, kgoff, koffh, aptr, sm, lane, acc);
            // publish partial sums
#pragma unroll
            for (int h = 0; h < 4; h++) {
                float4 v; v.x = acc[h][0]; v.y = acc[h][1]; v.z = acc[h][2]; v.w = acc[h][3];
                sm->redsum[wq][h][lane] = v;
            }
        }

        __syncthreads();   // redsum visible

        if (half == 0) {
#pragma unroll
            for (int h = 0; h < 4; h++) {
                float4 rr = sm->redsum[wq][h][lane];
                acc[h][0] += rr.x; acc[h][1] += rr.y;
                acc[h][2] += rr.z; acc[h][3] += rr.w;
            }
            // epilogue: leak-integrate, write out[t] + fp16 scratch[wsel]
            float*  op  = out + (size_t)t * FRAME + rowoff;
            __half* scw = g_scratch[wsel] + rowoff;
#pragma unroll
            for (int h = 0; h < 4; h++) {
                int col = h * 8 + c0;
                float2 nA = nzv[h * 2], nB = nzv[h * 2 + 1];
                float s0 = OMA_F * stprev[h][0] + ALPHA_F * (acc[h][0] + SIGMA_F * nA.x);
                float s1 = OMA_F * stprev[h][1] + ALPHA_F * (acc[h][1] + SIGMA_F * nA.y);
                float s2 = OMA_F * stprev[h][2] + ALPHA_F * (acc[h][2] + SIGMA_F * nB.x);
                float s3 = OMA_F * stprev[h][3] + ALPHA_F * (acc[h][3] + SIGMA_F * nB.y);
                float2 oA; oA.x = s0; oA.y = s1;
                float2 oB; oB.x = s2; oB.y = s3;
                *reinterpret_cast<float2*>(op + col)            = oA;
                *reinterpret_cast<float2*>(op + 8 * HDIM + col) = oB;
                *reinterpret_cast<__half2*>(scw + col) =
                    __floats2half2_rn(fmaxf(s0, 0.0f), fmaxf(s1, 0.0f));
                *reinterpret_cast<__half2*>(scw + 8 * HDIM + col) =
                    __floats2half2_rn(fmaxf(s2, 0.0f), fmaxf(s3, 0.0f));
                stprev[h][0] = s0; stprev[h][1] = s1;
                stprev[h][2] = s2; stprev[h][3] = s3;
            }
        }

        if (t < T_STEPS) grid_barrier();   // publish scratch[wsel]
    }
}

extern "C" void kernel_launch(void* const* d_in, const int* in_sizes, int n_in,
                              void* d_out, int out_size) {
    const float* x     = (const float*)d_in[0];
    const float* init  = (const float*)d_in[1];
    const float* noise = (const float*)d_in[2];
    const float* wih   = (const float*)d_in[3];
    const float* whh   = (const float*)d_in[4];
    const float* bias  = (const float*)d_in[5];
    float* out = (float*)d_out;

    cudaFuncSetAttribute(rnn_kernel, cudaFuncAttributeMaxDynamicSharedMemorySize,
                         (int)sizeof(SmemLayout));
    rnn_kernel<<<NCTA, THREADS, sizeof(SmemLayout)>>>(x, init, noise, wih, whh, bias, out);
}

// round 9
// speedup vs baseline: 2.3529x; 1.8818x over previous
#include <cuda_runtime.h>
#include <cuda_fp16.h>
#include <cstdint>

#define T_STEPS 1000
#define HDIM    512
#define IDIM    13
#define FRAME   (512 * 512)

#define NT      16          // tiles along H (N); also CTAs per row-group
#define NCTA    128         // 8 row-groups x 16
#define GROUPN  16
#define THREADS 256         // warps 0-3: K[0,256); warps 4-7: K[256,512)
#define ASTRH   520         // padded A row in halves

#define ALPHA_F 0.2f
#define OMA_F   0.8f
#define SIGMA_F 0.15811388300841898f   // sqrt(2/0.2)*0.05

struct SmemLayout {
    __half a[64][ASTRH];          // relu'd fp16 prev-state tile rows
    uint2  wfrag[32][4][32];      // W_hh B-fragments (fp16x2 pairs)
    float4 redsum[4][4][32];      // half0 partial sums (incl bias + xWih)
    float  xs[64 * IDIM];         // staged x rows (packed)
    float  wih[IDIM][32];         // W_ih column slice
    float  biass[32];
};

__device__ __half   g_scratch[2][FRAME];    // relu'd fp16 state, double buffered
__device__ unsigned g_sync[8 * 64];         // per-group: [g*64]=count, [g*64+32]=phase

__device__ __forceinline__ void group_barrier(int grp) {
    __syncthreads();
    if (threadIdx.x == 0) {
        unsigned* cnt = &g_sync[grp * 64];
        unsigned* phs = &g_sync[grp * 64 + 32];
        unsigned ph;
        asm volatile("ld.acquire.gpu.u32 %0, [%1];" : "=r"(ph) : "l"(phs) : "memory");
        unsigned arrived;
        asm volatile("atom.acq_rel.gpu.add.u32 %0, [%1], %2;"
                     : "=r"(arrived) : "l"(cnt), "r"(1u) : "memory");
        if (arrived == GROUPN - 1) {
            asm volatile("st.relaxed.gpu.u32 [%0], %1;" :: "l"(cnt), "r"(0u) : "memory");
            asm volatile("red.release.gpu.add.u32 [%0], %1;" :: "l"(phs), "r"(1u) : "memory");
        } else {
            unsigned cur;
            do {
                asm volatile("ld.acquire.gpu.u32 %0, [%1];" : "=r"(cur) : "l"(phs) : "memory");
            } while (cur == ph);
        }
    }
    __syncthreads();
}

template <int N>
__device__ __forceinline__ void wait_cp() {
    asm volatile("cp.async.wait_group %0;" :: "n"(N) : "memory");
}

#define MMA_F16(D, A0, A1, A2, A3, B0, B1)                                       \
    asm volatile("mma.sync.aligned.m16n8k16.row.col.f32.f16.f16.f32 "            \
                 "{%0,%1,%2,%3}, {%4,%5,%6,%7}, {%8,%9}, {%0,%1,%2,%3};"         \
                 : "+f"(D[0]), "+f"(D[1]), "+f"(D[2]), "+f"(D[3])                 \
                 : "r"(A0), "r"(A1), "r"(A2), "r"(A3), "r"(B0), "r"(B1))

__global__ void __launch_bounds__(THREADS, 1)
rnn_kernel(const float* __restrict__ x,       // [T,B,13]
           const float* __restrict__ init,    // [B,H]
           const float* __restrict__ noise,   // [T,B,H]
           const float* __restrict__ wih_g,   // [13,H]
           const float* __restrict__ whh_g,   // [H,H]
           const float* __restrict__ bias_g,  // [1,H]
           float* __restrict__ out)           // [T+1,B,H]
{
    extern __shared__ char smem_raw[];
    SmemLayout* sm = reinterpret_cast<SmemLayout*>(smem_raw);

    const int tid  = threadIdx.x;
    const int mt   = blockIdx.x / NT;     // row-group id
    const int nt   = blockIdx.x % NT;
    const int m0   = mt * 64;
    const int n0   = nt * 32;
    const int wid  = tid >> 5;
    const int lane = tid & 31;
    const int half = wid >> 2;            // 0: K[0,256)  1: K[256,512) + epilogue
    const int wq   = wid & 3;             // m-block within tile
    const int G    = lane >> 2;
    const int T4   = lane & 3;
    const int c0   = T4 * 2;
    const int r0l  = wq * 16 + G;
    const int koffh = half * 256;
    const int kgoff = half * 16;

    // ---------------- one-time setup ----------------
    for (int i = tid; i < IDIM * 32; i += THREADS) {
        int r = i / 32, c = i % 32;
        sm->wih[r][c] = wih_g[r * HDIM + n0 + c];
    }
    if (tid < 32) sm->biass[tid] = bias_g[n0 + tid];

    // W_hh fragments (fp16, diag masked), m16n8k16 B layout
    for (int i = tid; i < 32 * 4 * 32; i += THREADS) {
        int ln = i & 31, h = (i >> 5) & 3, kc = i >> 7;
        int Tl = ln & 3, Gl = ln >> 2;
        int n  = n0 + h * 8 + Gl;
        int kb = kc * 16 + 2 * Tl;
        float v00 = (kb     == n) ? 0.0f : whh_g[(size_t)kb * HDIM + n];
        float v01 = (kb + 1 == n) ? 0.0f : whh_g[(size_t)(kb + 1) * HDIM + n];
        float v10 = (kb + 8 == n) ? 0.0f : whh_g[(size_t)(kb + 8) * HDIM + n];
        float v11 = (kb + 9 == n) ? 0.0f : whh_g[(size_t)(kb + 9) * HDIM + n];
        __half2 p0 = __floats2half2_rn(v00, v01);
        __half2 p1 = __floats2half2_rn(v10, v11);
        uint2 p;
        p.x = *reinterpret_cast<unsigned*>(&p0);
        p.y = *reinterpret_cast<unsigned*>(&p1);
        sm->wfrag[kc][h][ln] = p;
    }

    // out[0] = init ; scratch[0] = fp16(relu(init))  (own 64x32 tile)
    for (int i = tid; i < 64 * 32; i += THREADS) {
        int r = i >> 5, c = i & 31;
        size_t gi = (size_t)(m0 + r) * HDIM + n0 + c;
        float v = init[gi];
        out[gi] = v;
        g_scratch[0][gi] = __float2half_rn(fmaxf(v, 0.0f));
    }

    // stprev registers live in half1 (epilogue owner)
    float stprev[4][4];
    if (half == 1) {
        const float* ip = init + (size_t)(m0 + r0l) * HDIM + n0;
#pragma unroll
        for (int h = 0; h < 4; h++) {
            int col = h * 8 + c0;
            float2 a = *reinterpret_cast<const float2*>(ip + col);
            float2 b = *reinterpret_cast<const float2*>(ip + 8 * HDIM + col);
            stprev[h][0] = a.x; stprev[h][1] = a.y;
            stprev[h][2] = b.x; stprev[h][3] = b.y;
        }
    }

    group_barrier(mt);

    const unsigned a_base = (unsigned)__cvta_generic_to_shared(&sm->a[0][0]);
    const __half* aptr = &sm->a[r0l][c0];
    const size_t rowoff = (size_t)(m0 + r0l) * HDIM + n0;
    // warp-local staging bases
    const unsigned s_base = a_base + (unsigned)(((16 * wq) * ASTRH + koffh + 8 * lane) * 2);

    for (int t = 1; t <= T_STEPS; t++) {
        const int rsel = (t - 1) & 1, wsel = t & 1;

        float2 nzv[8];
        if (half == 1) {
            // prefetch noise into registers (lands during GEMM)
            const float* nz = noise + (size_t)(t - 1) * FRAME + rowoff;
#pragma unroll
            for (int h = 0; h < 4; h++) {
                nzv[h * 2]     = *reinterpret_cast<const float2*>(nz + h * 8 + c0);
                nzv[h * 2 + 1] = *reinterpret_cast<const float2*>(nz + 8 * HDIM + h * 8 + c0);
            }
        } else {
            // warp-local x staging: rows [16wq, 16wq+16)
            const float* xq = x + ((size_t)(t - 1) * 512 + m0 + 16 * wq) * IDIM;
            float* xsw = &sm->xs[16 * wq * IDIM];
#pragma unroll
            for (int i = lane; i < 16 * IDIM; i += 32) xsw[i] = xq[i];
        }

        // ---- warp-local A staging: 16 rows x 256 half-cols, one group ----
        {
            const __half* srcw = g_scratch[rsel] +
                                 (size_t)(m0 + 16 * wq) * HDIM + koffh + 8 * lane;
#pragma unroll
            for (int j = 0; j < 16; j++) {
                asm volatile("cp.async.cg.shared.global [%0], [%1], 16;"
                             :: "r"(s_base + (unsigned)(j * ASTRH * 2)),
                                "l"(srcw + (size_t)j * HDIM) : "memory");
            }
            asm volatile("cp.async.commit_group;" ::: "memory");
        }

        wait_cp<0>();
        __syncwarp();        // own A block + (half0) xs visible warp-wide

        // ---- 16 k16 MMA steps over own K-half ----
        float acc[4][4];
#pragma unroll
        for (int h = 0; h < 4; h++)
            acc[h][0] = acc[h][1] = acc[h][2] = acc[h][3] = 0.0f;
#pragma unroll
        for (int kcl = 0; kcl < 16; kcl++) {
            const int kb = koffh + kcl * 16;
            unsigned u0 = *reinterpret_cast<const unsigned*>(aptr + kb);
            unsigned u1 = *reinterpret_cast<const unsigned*>(aptr + 8 * ASTRH + kb);
            unsigned u2 = *reinterpret_cast<const unsigned*>(aptr + kb + 8);
            unsigned u3 = *reinterpret_cast<const unsigned*>(aptr + 8 * ASTRH + kb + 8);
#pragma unroll
            for (int h = 0; h < 4; h++) {
                uint2 b = sm->wfrag[kgoff + kcl][h][lane];
                MMA_F16(acc[h], u0, u1, u2, u3, b.x, b.y);
            }
        }

        if (half == 0) {
            // add bias + x @ W_ih, publish partial, hand off to half1
#pragma unroll
            for (int h = 0; h < 4; h++) {
                int col = h * 8 + c0;
                acc[h][0] += sm->biass[col];     acc[h][1] += sm->biass[col + 1];
                acc[h][2] += sm->biass[col];     acc[h][3] += sm->biass[col + 1];
            }
#pragma unroll
            for (int i = 0; i < IDIM; i++) {
                float x0 = sm->xs[r0l * IDIM + i];
                float x1 = sm->xs[(r0l + 8) * IDIM + i];
#pragma unroll
                for (int h = 0; h < 4; h++) {
                    int col = h * 8 + c0;
                    float w0 = sm->wih[i][col], w1 = sm->wih[i][col + 1];
                    acc[h][0] += x0 * w0; acc[h][1] += x0 * w1;
                    acc[h][2] += x1 * w0; acc[h][3] += x1 * w1;
                }
            }
#pragma unroll
            for (int h = 0; h < 4; h++) {
                float4 v; v.x = acc[h][0]; v.y = acc[h][1]; v.z = acc[h][2]; v.w = acc[h][3];
                sm->redsum[wq][h][lane] = v;
            }
            asm volatile("bar.sync %0, 64;" :: "r"(1 + wq) : "memory");
        } else {
            asm volatile("bar.sync %0, 64;" :: "r"(1 + wq) : "memory");
#pragma unroll
            for (int h = 0; h < 4; h++) {
                float4 rr = sm->redsum[wq][h][lane];
                acc[h][0] += rr.x; acc[h][1] += rr.y;
                acc[h][2] += rr.z; acc[h][3] += rr.w;
            }
            // epilogue: leak-integrate, write out[t] + fp16 scratch[wsel]
            float*  op  = out + (size_t)t * FRAME + rowoff;
            __half* scw = g_scratch[wsel] + rowoff;
#pragma unroll
            for (int h = 0; h < 4; h++) {
                int col = h * 8 + c0;
                float2 nA = nzv[h * 2], nB = nzv[h * 2 + 1];
                float s0 = OMA_F * stprev[h][0] + ALPHA_F * (acc[h][0] + SIGMA_F * nA.x);
                float s1 = OMA_F * stprev[h][1] + ALPHA_F * (acc[h][1] + SIGMA_F * nA.y);
                float s2 = OMA_F * stprev[h][2] + ALPHA_F * (acc[h][2] + SIGMA_F * nB.x);
                float s3 = OMA_F * stprev[h][3] + ALPHA_F * (acc[h][3] + SIGMA_F * nB.y);
                float2 oA; oA.x = s0; oA.y = s1;
                float2 oB; oB.x = s2; oB.y = s3;
                *reinterpret_cast<float2*>(op + col)            = oA;
                *reinterpret_cast<float2*>(op + 8 * HDIM + col) = oB;
                *reinterpret_cast<__half2*>(scw + col) =
                    __floats2half2_rn(fmaxf(s0, 0.0f), fmaxf(s1, 0.0f));
                *reinterpret_cast<__half2*>(scw + 8 * HDIM + col) =
                    __floats2half2_rn(fmaxf(s2, 0.0f), fmaxf(s3, 0.0f));
                stprev[h][0] = s0; stprev[h][1] = s1;
                stprev[h][2] = s2; stprev[h][3] = s3;
            }
        }

        if (t < T_STEPS) group_barrier(mt);   // publish scratch[wsel] to own row-group
    }
}

extern "C" void kernel_launch(void* const* d_in, const int* in_sizes, int n_in,
                              void* d_out, int out_size) {
    const float* x     = (const float*)d_in[0];
    const float* init  = (const float*)d_in[1];
    const float* noise = (const float*)d_in[2];
    const float* wih   = (const float*)d_in[3];
    const float* whh   = (const float*)d_in[4];
    const float* bias  = (const float*)d_in[5];
    float* out = (float*)d_out;

    cudaFuncSetAttribute(rnn_kernel, cudaFuncAttributeMaxDynamicSharedMemorySize,
                         (int)sizeof(SmemLayout));
    rnn_kernel<<<NCTA, THREADS, sizeof(SmemLayout)>>>(x, init, noise, wih, whh, bias, out);
}

// round 10
// speedup vs baseline: 2.4448x; 1.0390x over previous
#include <cuda_runtime.h>
#include <cuda_fp16.h>
#include <cstdint>

#define T_STEPS 1000
#define HDIM    512
#define IDIM    13
#define FRAME   (512 * 512)

#define CLUSTER 16          // CTAs per row-group = cluster size (nonportable)
#define NCTA    128         // 8 row-groups x 16
#define THREADS 256         // warps 0-3: K[0,256); warps 4-7: K[256,512) + epilogue
#define ASTRH   520         // padded A row in halves (1040 B, 16B-multiple)

#define ALPHA_F 0.2f
#define OMA_F   0.8f
#define SIGMA_F 0.15811388300841898f   // sqrt(2/0.2)*0.05

struct SmemLayout {
    __half a[64][ASTRH];            // relu'd fp16 prev-state tile rows
    uint2  wfrag[32][4][32];        // W_hh B-fragments (fp16x2 pairs)
    float4 redsum[4][4][32];        // half0 partial sums (incl bias + xWih)
    float  xs[64 * IDIM];           // staged x rows (packed)
    float  wih[IDIM][32];           // W_ih column slice
    float  biass[32];
    unsigned long long mbar[4];     // per-warp-pair cluster mbarriers
};

__device__ __half g_scratch[2][FRAME];   // relu'd fp16 state, double buffered

template <int N>
__device__ __forceinline__ void wait_cp() {
    asm volatile("cp.async.wait_group %0;" :: "n"(N) : "memory");
}

__device__ __forceinline__ unsigned smem_u32(const void* p) {
    return (unsigned)__cvta_generic_to_shared(p);
}

// spin on LOCAL smem mbarrier, acquire at cluster scope (orders peers' global stores)
__device__ __forceinline__ void mbar_wait_cluster(unsigned addr, unsigned parity) {
    asm volatile(
        "{\n\t"
        ".reg .pred P;\n\t"
        "WAIT_%=:\n\t"
        "mbarrier.try_wait.parity.acquire.cluster.shared::cta.b64 P, [%0], %1, 0x989680;\n\t"
        "@P bra.uni DONE_%=;\n\t"
        "bra.uni WAIT_%=;\n\t"
        "DONE_%=:\n\t"
        "}"
        :: "r"(addr), "r"(parity) : "memory");
}

// release-arrive on peer CTA `rank`'s mbarrier at the same smem offset
__device__ __forceinline__ void mbar_arrive_peer(unsigned local_addr, unsigned rank) {
    asm volatile(
        "{\n\t"
        ".reg .b32 r;\n\t"
        "mapa.shared::cluster.u32 r, %0, %1;\n\t"
        "mbarrier.arrive.release.cluster.shared::cluster.b64 _, [r];\n\t"
        "}"
        :: "r"(local_addr), "r"(rank) : "memory");
}

#define MMA_F16(D, A0, A1, A2, A3, B0, B1)                                       \
    asm volatile("mma.sync.aligned.m16n8k16.row.col.f32.f16.f16.f32 "            \
                 "{%0,%1,%2,%3}, {%4,%5,%6,%7}, {%8,%9}, {%0,%1,%2,%3};"         \
                 : "+f"(D[0]), "+f"(D[1]), "+f"(D[2]), "+f"(D[3])                 \
                 : "r"(A0), "r"(A1), "r"(A2), "r"(A3), "r"(B0), "r"(B1))

__global__ void __launch_bounds__(THREADS, 1)
rnn_kernel(const float* __restrict__ x,       // [T,B,13]
           const float* __restrict__ init,    // [B,H]
           const float* __restrict__ noise,   // [T,B,H]
           const float* __restrict__ wih_g,   // [13,H]
           const float* __restrict__ whh_g,   // [H,H]
           const float* __restrict__ bias_g,  // [1,H]
           float* __restrict__ out)           // [T+1,B,H]
{
    extern __shared__ char smem_raw[];
    SmemLayout* sm = reinterpret_cast<SmemLayout*>(smem_raw);

    const int tid  = threadIdx.x;
    unsigned rank;
    asm("mov.u32 %0, %%cluster_ctarank;" : "=r"(rank));
    const int mt   = blockIdx.x / CLUSTER;   // row-group id
    const int nt   = (int)rank;              // tile along H within group
    const int m0   = mt * 64;
    const int n0   = nt * 32;
    const int wid  = tid >> 5;
    const int lane = tid & 31;
    const int half = wid >> 2;               // 0: K[0,256)  1: K[256,512) + epilogue
    const int wq   = wid & 3;                // m-block within tile
    const int G    = lane >> 2;
    const int T4   = lane & 3;
    const int c0   = T4 * 2;
    const int r0l  = wq * 16 + G;
    const int koffh = half * 256;
    const int kgoff = half * 16;

    // ---------------- one-time setup ----------------
    if (tid == 0) {
#pragma unroll
        for (int q = 0; q < 4; q++) {
            unsigned a = smem_u32(&sm->mbar[q]);
            asm volatile("mbarrier.init.shared.b64 [%0], %1;" :: "r"(a), "r"(16u) : "memory");
        }
    }

    for (int i = tid; i < IDIM * 32; i += THREADS) {
        int r = i / 32, c = i % 32;
        sm->wih[r][c] = wih_g[r * HDIM + n0 + c];
    }
    if (tid < 32) sm->biass[tid] = bias_g[n0 + tid];

    // W_hh fragments (fp16, diag masked), m16n8k16 B layout
    for (int i = tid; i < 32 * 4 * 32; i += THREADS) {
        int ln = i & 31, h = (i >> 5) & 3, kc = i >> 7;
        int Tl = ln & 3, Gl = ln >> 2;
        int n  = n0 + h * 8 + Gl;
        int kb = kc * 16 + 2 * Tl;
        float v00 = (kb     == n) ? 0.0f : whh_g[(size_t)kb * HDIM + n];
        float v01 = (kb + 1 == n) ? 0.0f : whh_g[(size_t)(kb + 1) * HDIM + n];
        float v10 = (kb + 8 == n) ? 0.0f : whh_g[(size_t)(kb + 8) * HDIM + n];
        float v11 = (kb + 9 == n) ? 0.0f : whh_g[(size_t)(kb + 9) * HDIM + n];
        __half2 p0 = __floats2half2_rn(v00, v01);
        __half2 p1 = __floats2half2_rn(v10, v11);
        uint2 p;
        p.x = *reinterpret_cast<unsigned*>(&p0);
        p.y = *reinterpret_cast<unsigned*>(&p1);
        sm->wfrag[kc][h][ln] = p;
    }

    // out[0] = init ; scratch[0] = fp16(relu(init))  (own 64x32 tile)
    for (int i = tid; i < 64 * 32; i += THREADS) {
        int r = i >> 5, c = i & 31;
        size_t gi = (size_t)(m0 + r) * HDIM + n0 + c;
        float v = init[gi];
        out[gi] = v;
        g_scratch[0][gi] = __float2half_rn(fmaxf(v, 0.0f));
    }

    // stprev registers live in half1 (epilogue owner)
    float stprev[4][4];
    if (half == 1) {
        const float* ip = init + (size_t)(m0 + r0l) * HDIM + n0;
#pragma unroll
        for (int h = 0; h < 4; h++) {
            int col = h * 8 + c0;
            float2 a = *reinterpret_cast<const float2*>(ip + col);
            float2 b = *reinterpret_cast<const float2*>(ip + 8 * HDIM + col);
            stprev[h][0] = a.x; stprev[h][1] = a.y;
            stprev[h][2] = b.x; stprev[h][3] = b.y;
        }
    }

    __syncthreads();
    // cluster-wide: mbarrier init + scratch[0] (global) visible to all peers
    asm volatile("barrier.cluster.arrive.aligned;" ::: "memory");
    asm volatile("barrier.cluster.wait.aligned;" ::: "memory");

    const unsigned a_base    = smem_u32(&sm->a[0][0]);
    const unsigned mbar_addr = smem_u32(&sm->mbar[wq]);
    const __half* aptr = &sm->a[r0l][c0];
    const size_t rowoff = (size_t)(m0 + r0l) * HDIM + n0;
    const unsigned s_base = a_base + (unsigned)(((16 * wq) * ASTRH + koffh + 8 * lane) * 2);

    for (int t = 1; t <= T_STEPS; t++) {
        const int rsel = (t - 1) & 1, wsel = t & 1;

        float2 nzv[8];
        if (half == 1) {
            // prefetch noise (independent of peers; lands during GEMM)
            const float* nz = noise + (size_t)(t - 1) * FRAME + rowoff;
#pragma unroll
            for (int h = 0; h < 4; h++) {
                nzv[h * 2]     = *reinterpret_cast<const float2*>(nz + h * 8 + c0);
                nzv[h * 2 + 1] = *reinterpret_cast<const float2*>(nz + 8 * HDIM + h * 8 + c0);
            }
        } else {
            // warp-local x staging: rows [16wq, 16wq+16)
            const float* xq = x + ((size_t)(t - 1) * 512 + m0 + 16 * wq) * IDIM;
            float* xsw = &sm->xs[16 * wq * IDIM];
#pragma unroll
            for (int i = lane; i < 16 * IDIM; i += 32) xsw[i] = xq[i];
        }

        // wait for all 16 peers' row-slice publications (local smem spin)
        if (t >= 2) mbar_wait_cluster(mbar_addr, (unsigned)(t & 1));

        // ---- warp-local A staging: 16 rows x 256 half-cols ----
        {
            const __half* srcw = g_scratch[rsel] +
                                 (size_t)(m0 + 16 * wq) * HDIM + koffh + 8 * lane;
#pragma unroll
            for (int j = 0; j < 16; j++) {
                asm volatile("cp.async.cg.shared.global [%0], [%1], 16;"
                             :: "r"(s_base + (unsigned)(j * ASTRH * 2)),
                                "l"(srcw + (size_t)j * HDIM) : "memory");
            }
            asm volatile("cp.async.commit_group;" ::: "memory");
        }
        wait_cp<0>();
        __syncwarp();

        // ---- 16 k16 MMA steps over own K-half ----
        float acc[4][4];
#pragma unroll
        for (int h = 0; h < 4; h++)
            acc[h][0] = acc[h][1] = acc[h][2] = acc[h][3] = 0.0f;
#pragma unroll
        for (int kcl = 0; kcl < 16; kcl++) {
            const int kb = koffh + kcl * 16;
            unsigned u0 = *reinterpret_cast<const unsigned*>(aptr + kb);
            unsigned u1 = *reinterpret_cast<const unsigned*>(aptr + 8 * ASTRH + kb);
            unsigned u2 = *reinterpret_cast<const unsigned*>(aptr + kb + 8);
            unsigned u3 = *reinterpret_cast<const unsigned*>(aptr + 8 * ASTRH + kb + 8);
#pragma unroll
            for (int h = 0; h < 4; h++) {
                uint2 b = sm->wfrag[kgoff + kcl][h][lane];
                MMA_F16(acc[h], u0, u1, u2, u3, b.x, b.y);
            }
        }

        if (half == 0) {
            // add bias + x @ W_ih, publish partial to pair warp
#pragma unroll
            for (int h = 0; h < 4; h++) {
                int col = h * 8 + c0;
                acc[h][0] += sm->biass[col];     acc[h][1] += sm->biass[col + 1];
                acc[h][2] += sm->biass[col];     acc[h][3] += sm->biass[col + 1];
            }
#pragma unroll
            for (int i = 0; i < IDIM; i++) {
                float x0 = sm->xs[r0l * IDIM + i];
                float x1 = sm->xs[(r0l + 8) * IDIM + i];
#pragma unroll
                for (int h = 0; h < 4; h++) {
                    int col = h * 8 + c0;
                    float w0 = sm->wih[i][col], w1 = sm->wih[i][col + 1];
                    acc[h][0] += x0 * w0; acc[h][1] += x0 * w1;
                    acc[h][2] += x1 * w0; acc[h][3] += x1 * w1;
                }
            }
#pragma unroll
            for (int h = 0; h < 4; h++) {
                float4 v; v.x = acc[h][0]; v.y = acc[h][1]; v.z = acc[h][2]; v.w = acc[h][3];
                sm->redsum[wq][h][lane] = v;
            }
            asm volatile("bar.sync %0, 64;" :: "r"(1 + wq) : "memory");
        } else {
            asm volatile("bar.sync %0, 64;" :: "r"(1 + wq) : "memory");
#pragma unroll
            for (int h = 0; h < 4; h++) {
                float4 rr = sm->redsum[wq][h][lane];
                acc[h][0] += rr.x; acc[h][1] += rr.y;
                acc[h][2] += rr.z; acc[h][3] += rr.w;
            }
            // epilogue: leak-integrate; scratch first (gates peers), out after
            __half* scw = g_scratch[wsel] + rowoff;
            float s[4][4];
#pragma unroll
            for (int h = 0; h < 4; h++) {
                int col = h * 8 + c0;
                float2 nA = nzv[h * 2], nB = nzv[h * 2 + 1];
                s[h][0] = OMA_F * stprev[h][0] + ALPHA_F * (acc[h][0] + SIGMA_F * nA.x);
                s[h][1] = OMA_F * stprev[h][1] + ALPHA_F * (acc[h][1] + SIGMA_F * nA.y);
                s[h][2] = OMA_F * stprev[h][2] + ALPHA_F * (acc[h][2] + SIGMA_F * nB.x);
                s[h][3] = OMA_F * stprev[h][3] + ALPHA_F * (acc[h][3] + SIGMA_F * nB.y);
                *reinterpret_cast<__half2*>(scw + col) =
                    __floats2half2_rn(fmaxf(s[h][0], 0.0f), fmaxf(s[h][1], 0.0f));
                *reinterpret_cast<__half2*>(scw + 8 * HDIM + col) =
                    __floats2half2_rn(fmaxf(s[h][2], 0.0f), fmaxf(s[h][3], 0.0f));
                stprev[h][0] = s[h][0]; stprev[h][1] = s[h][1];
                stprev[h][2] = s[h][2]; stprev[h][3] = s[h][3];
            }
            __syncwarp();                       // all lanes' scratch stores ordered
            if (t < T_STEPS && lane < CLUSTER)
                mbar_arrive_peer(mbar_addr, (unsigned)lane);   // 16 parallel release-arrives

            // out[t] stores off the critical path
            float* op = out + (size_t)t * FRAME + rowoff;
#pragma unroll
            for (int h = 0; h < 4; h++) {
                int col = h * 8 + c0;
                float2 oA; oA.x = s[h][0]; oA.y = s[h][1];
                float2 oB; oB.x = s[h][2]; oB.y = s[h][3];
                *reinterpret_cast<float2*>(op + col)            = oA;
                *reinterpret_cast<float2*>(op + 8 * HDIM + col) = oB;
            }
        }
    }

    // no CTA may exit while peers could still address its smem
    asm volatile("barrier.cluster.arrive.aligned;" ::: "memory");
    asm volatile("barrier.cluster.wait.aligned;" ::: "memory");
}

extern "C" void kernel_launch(void* const* d_in, const int* in_sizes, int n_in,
                              void* d_out, int out_size) {
    const float* x     = (const float*)d_in[0];
    const float* init  = (const float*)d_in[1];
    const float* noise = (const float*)d_in[2];
    const float* wih   = (const float*)d_in[3];
    const float* whh   = (const float*)d_in[4];
    const float* bias  = (const float*)d_in[5];
    float* out = (float*)d_out;

    cudaFuncSetAttribute(rnn_kernel, cudaFuncAttributeMaxDynamicSharedMemorySize,
                         (int)sizeof(SmemLayout));
    cudaFuncSetAttribute(rnn_kernel, cudaFuncAttributeNonPortableClusterSizeAllowed, 1);

    cudaLaunchConfig_t cfg = {};
    cfg.gridDim  = dim3(NCTA, 1, 1);
    cfg.blockDim = dim3(THREADS, 1, 1);
    cfg.dynamicSmemBytes = sizeof(SmemLayout);
    cfg.stream = 0;
    cudaLaunchAttribute attrs[1];
    attrs[0].id = cudaLaunchAttributeClusterDimension;
    attrs[0].val.clusterDim.x = CLUSTER;
    attrs[0].val.clusterDim.y = 1;
    attrs[0].val.clusterDim.z = 1;
    cfg.attrs = attrs;
    cfg.numAttrs = 1;
    cudaLaunchKernelEx(&cfg, rnn_kernel, x, init, noise, wih, whh, bias, out);
}